// round 5
// baseline (speedup 1.0000x reference)
#include <cuda_runtime.h>
#include <cuda_bf16.h>

// ---------------- problem constants ----------------
#define B_  64
#define H_  512
#define W_  512
#define RAD 20
#define KSZ 41

// ---------------- Gaussian weights (compile-time) ----------------
constexpr double PHI[21] = {
    1.0,
    0.98019867, 0.92311635, 0.83527021, 0.72614903, 0.60653066,
    0.48675227, 0.37531110, 0.27803730, 0.19789870, 0.13533528,
    0.08892161, 0.05613478, 0.03404747, 0.01984109, 0.01110900,
    0.00597603, 0.00308871, 0.00153381, 0.00073181, 0.00033546
};

constexpr double ksum() {
    double s = PHI[0];
    for (int t = 1; t <= 20; ++t) s += 2.0 * PHI[t];
    return s;
}

struct W41x2 { float2 v[KSZ]; };

constexpr W41x2 make_w2(double scale) {
    W41x2 w{};
    double s = ksum();
    for (int i = 0; i < KSZ; ++i) {
        int t = i - RAD; if (t < 0) t = -t;
        float f = (float)(scale * PHI[t] / s);
        w.v[i].x = f; w.v[i].y = f;
    }
    return w;
}

__constant__ W41x2 WH2 = make_w2(1.0);    // h-pass
__constant__ W41x2 WV2 = make_w2(100.0);  // v-pass folds 2*ALPHA; subtract ALPHA later

// packed f32x2 FMA (sm_100+)
__device__ __forceinline__ void fma2(float2& acc, const float2 v, const float2 w) {
    asm("fma.rn.f32x2 %0, %1, %2, %0;"
        : "+l"(reinterpret_cast<unsigned long long&>(acc))
        : "l"(reinterpret_cast<const unsigned long long&>(v)),
          "l"(reinterpret_cast<const unsigned long long&>(w)));
}

// ---------------- interleaved scratch: (dx,dy) pairs ----------------
__device__ float2 g_t[(size_t)B_ * H_ * W_];

__device__ __forceinline__ int reflect_once(int i, int n) {
    i = (i < 0) ? (-1 - i) : i;
    return (i >= n) ? (2 * n - 1 - i) : i;
}

// fast reflect for gather coords: valid for i in [-512, 1023], n=512
__device__ __forceinline__ int reflect_fast(int i) {
    return ((unsigned)i < (unsigned)W_) ? i : (~i & (2 * W_ - 1));
}

// ================= kernel 1: horizontal blur =================
#define HS_STR 33

__global__ __launch_bounds__(128, 10) void hblur_kernel(
    const float* __restrict__ rdx, const float* __restrict__ rdy)
{
    __shared__ float2 s[72 * HS_STR];   // 19,008 B

    const int r   = threadIdx.x;             // 0..31 row lane
    const int ty  = threadIdx.y;             // 0..3 col chunk
    const int tid = ty * 32 + r;
    const int c0   = blockIdx.x * 32;        // first output col
    const int row0 = blockIdx.y * 32;        // first row
    const int b    = blockIdx.z;
    const size_t base = (size_t)b * H_ * W_;

    // halo: 72 window cols x 32 rows; div-free, coalesced on col
    {
        const int lc = tid & 31;
        const int lr = tid >> 5;
        #pragma unroll
        for (int q = 0; q < 3; ++q) {
            const int cc = lc + 32 * q;
            if (cc < 72) {
                const int gc = reflect_once(c0 - RAD + cc, W_);
                #pragma unroll
                for (int m = 0; m < 8; ++m) {
                    const int rr = lr + 4 * m;
                    const size_t g = base + (size_t)(row0 + rr) * W_ + gc;
                    s[cc * HS_STR + rr] = make_float2(rdx[g], rdy[g]);
                }
            }
        }
    }
    __syncthreads();

    const int x0 = ty * 8;
    float2 acc[8] = {};
    float2 win[8];
    #pragma unroll
    for (int k = 0; k < 8; ++k) win[k] = s[(x0 + k) * HS_STR + r];

    #pragma unroll
    for (int t = 0; t < KSZ; ++t) {
        // prefetch next window element BEFORE the FMA batch
        float2 nxt;
        if (t < KSZ - 1) nxt = s[(x0 + t + 8) * HS_STR + r];
        const float2 w = WH2.v[t];
        #pragma unroll
        for (int j = 0; j < 8; ++j)
            fma2(acc[j], win[(t + j) & 7], w);
        if (t < KSZ - 1) win[t & 7] = nxt;
    }
    __syncthreads();

    // transpose through smem: s2[r*41 + c] (stride 41 -> conflict-free)
    float2* s2 = s;
    #pragma unroll
    for (int j = 0; j < 8; ++j)
        s2[r * 41 + x0 + j] = acc[j];
    __syncthreads();

    #pragma unroll
    for (int m = 0; m < 8; ++m) {
        const int i  = m * 128 + tid;
        const int rr = i >> 5;
        const int cc = i & 31;
        g_t[base + (size_t)(row0 + rr) * W_ + c0 + cc] = s2[rr * 41 + cc];
    }
}

// ================= kernel 2: vertical blur + warp =================
#define VS_STR 73

__global__ __launch_bounds__(128, 9) void vwarp_kernel(
    const float* __restrict__ img, float* __restrict__ out)
{
    __shared__ float2 s[32 * VS_STR];   // 18,688 B

    const int tx = threadIdx.x;
    const int ty = threadIdx.y;
    const int x  = blockIdx.x * 32 + tx;
    const int y0 = blockIdx.y * 32;
    const int b  = blockIdx.z;
    const size_t base = (size_t)b * H_ * W_;
    const float2* gt = g_t + base;

    // halo: 72 rows of this block's 32 cols, coalesced on x
    #pragma unroll
    for (int j = ty; j < 32 + 2 * RAD; j += 4) {
        const int y = reflect_once(y0 + j - RAD, H_);
        s[tx * VS_STR + j] = __ldg(&gt[(size_t)y * W_ + x]);
    }
    __syncthreads();

    const int r0 = ty * 8;
    float2 acc[8] = {};
    float2 win[8];
    #pragma unroll
    for (int k = 0; k < 8; ++k) win[k] = s[tx * VS_STR + r0 + k];

    #pragma unroll
    for (int t = 0; t < KSZ; ++t) {
        float2 nxt;
        if (t < KSZ - 1) nxt = s[tx * VS_STR + r0 + t + 8];
        const float2 w = WV2.v[t];
        #pragma unroll
        for (int j = 0; j < 8; ++j)
            fma2(acc[j], win[(t + j) & 7], w);
        if (t < KSZ - 1) win[t & 7] = nxt;
    }

    const float* im = img + base;
    const float xbase = (float)x - 50.0f;   // fold (2*ALPHA*blur - ALPHA)

    // gather in two 4-px phases; each phase: all 16 offsets, then all 16 loads
    #pragma unroll
    for (int g = 0; g < 2; ++g) {
        int   o00[4], o01[4], o10[4], o11[4];
        float wxa[4], wya[4];
        #pragma unroll
        for (int j = 0; j < 4; ++j) {
            const int jj = g * 4 + j;
            const int yo = y0 + r0 + jj;
            const float xx = xbase + acc[jj].x;
            const float yy = (float)yo - 50.0f + acc[jj].y;
            const int xi = __float2int_rd(xx);
            const int yi = __float2int_rd(yy);
            wxa[j] = xx - (float)xi;
            wya[j] = yy - (float)yi;
            const int x0r = reflect_fast(xi);
            const int x1r = reflect_fast(xi + 1);
            const int y0r = reflect_fast(yi);
            const int y1r = reflect_fast(yi + 1);
            o00[j] = y0r * W_ + x0r;
            o01[j] = y0r * W_ + x1r;
            o10[j] = y1r * W_ + x0r;
            o11[j] = y1r * W_ + x1r;
        }
        float v00[4], v01[4], v10[4], v11[4];
        #pragma unroll
        for (int j = 0; j < 4; ++j) {
            v00[j] = __ldg(im + o00[j]);
            v01[j] = __ldg(im + o01[j]);
            v10[j] = __ldg(im + o10[j]);
            v11[j] = __ldg(im + o11[j]);
        }
        #pragma unroll
        for (int j = 0; j < 4; ++j) {
            const int jj = g * 4 + j;
            const int yo = y0 + r0 + jj;
            const float top = fmaf(wxa[j], v01[j] - v00[j], v00[j]);
            const float bot = fmaf(wxa[j], v11[j] - v10[j], v10[j]);
            out[base + (size_t)yo * W_ + x] = fmaf(wya[j], bot - top, top);
        }
    }
}

// ---------------- launch ----------------
extern "C" void kernel_launch(void* const* d_in, const int* in_sizes, int n_in,
                              void* d_out, int out_size)
{
    const float* x       = (const float*)d_in[0];  // [B,1,H,W]
    const float* rand_dx = (const float*)d_in[1];  // [B,H,W]
    const float* rand_dy = (const float*)d_in[2];  // [B,H,W]
    float* out = (float*)d_out;

    {
        dim3 grid(W_ / 32, H_ / 32, B_);
        dim3 block(32, 4);
        hblur_kernel<<<grid, block>>>(rand_dx, rand_dy);
    }
    {
        dim3 grid(W_ / 32, H_ / 32, B_);
        dim3 block(32, 4);
        vwarp_kernel<<<grid, block>>>(x, out);
    }
}

// round 7
// speedup vs baseline: 1.1514x; 1.1514x over previous
#include <cuda_runtime.h>
#include <cuda_bf16.h>

// ---------------- problem constants ----------------
#define B_  64
#define H_  512
#define W_  512
#define RAD 20
#define KSZ 41

// ---------------- Gaussian weights (compile-time) ----------------
constexpr double PHI[21] = {
    1.0,
    0.98019867, 0.92311635, 0.83527021, 0.72614903, 0.60653066,
    0.48675227, 0.37531110, 0.27803730, 0.19789870, 0.13533528,
    0.08892161, 0.05613478, 0.03404747, 0.01984109, 0.01110900,
    0.00597603, 0.00308871, 0.00153381, 0.00073181, 0.00033546
};

constexpr double ksum() {
    double s = PHI[0];
    for (int t = 1; t <= 20; ++t) s += 2.0 * PHI[t];
    return s;
}

struct W41x2 { float2 v[KSZ]; };

constexpr W41x2 make_w2(double scale) {
    W41x2 w{};
    double s = ksum();
    for (int i = 0; i < KSZ; ++i) {
        int t = i - RAD; if (t < 0) t = -t;
        float f = (float)(scale * PHI[t] / s);
        w.v[i].x = f; w.v[i].y = f;
    }
    return w;
}

__constant__ W41x2 WH2 = make_w2(1.0);    // h-pass
__constant__ W41x2 WV2 = make_w2(100.0);  // v-pass folds 2*ALPHA; subtract ALPHA later

// packed f32x2 FMA (sm_100+)
__device__ __forceinline__ void fma2(float2& acc, const float2 v, const float2 w) {
    asm("fma.rn.f32x2 %0, %1, %2, %0;"
        : "+l"(reinterpret_cast<unsigned long long&>(acc))
        : "l"(reinterpret_cast<const unsigned long long&>(v)),
          "l"(reinterpret_cast<const unsigned long long&>(w)));
}

// ---------------- interleaved scratch: (dx,dy) pairs ----------------
__device__ float2 g_t[(size_t)B_ * H_ * W_];

__device__ __forceinline__ int reflect_once(int i, int n) {
    i = (i < 0) ? (-1 - i) : i;
    return (i >= n) ? (2 * n - 1 - i) : i;
}

// fast reflect for gather coords: valid for i in [-512, 1023], n=512
__device__ __forceinline__ int reflect_fast(int i) {
    return ((unsigned)i < (unsigned)W_) ? i : (~i & (2 * W_ - 1));
}

// ================= kernel 1: horizontal blur =================
// Tile 32 rows x 32 cols. block (32,8): threadIdx.x = row lane, ty = 4-col chunk.
// smem col-major s[cc*33 + r]: compute LDS.64 lane stride 8B (conflict-free).
#define HS_STR 33

__global__ __launch_bounds__(256) void hblur_kernel(
    const float* __restrict__ rdx, const float* __restrict__ rdy)
{
    __shared__ float2 s[72 * HS_STR];   // 19,008 B

    const int r   = threadIdx.x;             // 0..31 row lane
    const int ty  = threadIdx.y;             // 0..7 col chunk (4 cols each)
    const int tid = ty * 32 + r;
    const int c0   = blockIdx.x * 32;
    const int row0 = blockIdx.y * 32;
    const int b    = blockIdx.z;
    const size_t base = (size_t)b * H_ * W_;

    // halo: 72 window cols x 32 rows; div-free, coalesced on col
    {
        const int lc = tid & 31;
        const int lr = tid >> 5;             // 0..7
        #pragma unroll
        for (int q = 0; q < 3; ++q) {
            const int cc = lc + 32 * q;
            if (cc < 72) {
                const int gc = reflect_once(c0 - RAD + cc, W_);
                #pragma unroll
                for (int m = 0; m < 4; ++m) {
                    const int rr = lr + 8 * m;
                    const size_t g = base + (size_t)(row0 + rr) * W_ + gc;
                    s[cc * HS_STR + rr] = make_float2(rdx[g], rdy[g]);
                }
            }
        }
    }
    __syncthreads();

    const int x0 = ty * 4;                   // local first output col
    float2 acc[4] = {};
    float2 win[4];
    #pragma unroll
    for (int k = 0; k < 4; ++k) win[k] = s[(x0 + k) * HS_STR + r];

    #pragma unroll
    for (int t = 0; t < KSZ; ++t) {
        float2 nxt;
        if (t < KSZ - 1) nxt = s[(x0 + t + 4) * HS_STR + r];
        const float2 w = WH2.v[t];
        #pragma unroll
        for (int j = 0; j < 4; ++j)
            fma2(acc[j], win[(t + j) & 3], w);
        if (t < KSZ - 1) win[t & 3] = nxt;
    }
    __syncthreads();

    // transpose through smem: s2[r*41 + c] (stride 41 -> conflict-free)
    float2* s2 = s;
    #pragma unroll
    for (int j = 0; j < 4; ++j)
        s2[r * 41 + x0 + j] = acc[j];
    __syncthreads();

    // coalesced stores: 32x32 tile, 4 iterations
    #pragma unroll
    for (int m = 0; m < 4; ++m) {
        const int i  = m * 256 + tid;
        const int rr = i >> 5;
        const int cc = i & 31;
        g_t[base + (size_t)(row0 + rr) * W_ + c0 + cc] = s2[rr * 41 + cc];
    }
}

// ================= kernel 2: vertical blur + warp =================
// Tile 32 cols x 32 rows. block (32,8): tx = col, ty = 4-row chunk.
// smem col-major s[tx*73 + row]: conflict-free (word-stride 146 mod 32 = 18).
#define VS_STR 73

__global__ __launch_bounds__(256) void vwarp_kernel(
    const float* __restrict__ img, float* __restrict__ out)
{
    __shared__ float2 s[32 * VS_STR];   // 18,688 B

    const int tx = threadIdx.x;
    const int ty = threadIdx.y;          // 0..7
    const int x  = blockIdx.x * 32 + tx;
    const int y0 = blockIdx.y * 32;
    const int b  = blockIdx.z;
    const size_t base = (size_t)b * H_ * W_;
    const float2* gt = g_t + base;

    // halo: 72 rows of this block's 32 cols, coalesced on x; 9 iters
    #pragma unroll
    for (int j = ty; j < 32 + 2 * RAD; j += 8) {
        const int y = reflect_once(y0 + j - RAD, H_);
        s[tx * VS_STR + j] = __ldg(&gt[(size_t)y * W_ + x]);
    }
    __syncthreads();

    const int r0 = ty * 4;               // first output row (tile-local)
    float2 acc[4] = {};
    float2 win[4];
    #pragma unroll
    for (int k = 0; k < 4; ++k) win[k] = s[tx * VS_STR + r0 + k];

    #pragma unroll
    for (int t = 0; t < KSZ; ++t) {
        float2 nxt;
        if (t < KSZ - 1) nxt = s[tx * VS_STR + r0 + t + 4];
        const float2 w = WV2.v[t];
        #pragma unroll
        for (int j = 0; j < 4; ++j)
            fma2(acc[j], win[(t + j) & 3], w);
        if (t < KSZ - 1) win[t & 3] = nxt;
    }

    const float* im = img + base;
    const float xbase = (float)x - 50.0f;   // fold (2*ALPHA*blur - ALPHA)

    #pragma unroll
    for (int j = 0; j < 4; ++j) {
        const int yo = y0 + r0 + j;
        const float xx = xbase + acc[j].x;
        const float yy = (float)yo - 50.0f + acc[j].y;

        const int xi = __float2int_rd(xx);
        const int yi = __float2int_rd(yy);
        const float wx = xx - (float)xi;
        const float wy = yy - (float)yi;

        const int x0r = reflect_fast(xi);
        const int x1r = reflect_fast(xi + 1);
        const int y0r = reflect_fast(yi);   // H_==W_==512
        const int y1r = reflect_fast(yi + 1);

        const float* ra = im + (size_t)y0r * W_;
        const float* rb = im + (size_t)y1r * W_;
        const float v00 = __ldg(ra + x0r);
        const float v01 = __ldg(ra + x1r);
        const float v10 = __ldg(rb + x0r);
        const float v11 = __ldg(rb + x1r);

        const float top = fmaf(wx, v01 - v00, v00);
        const float bot = fmaf(wx, v11 - v10, v10);
        out[base + (size_t)yo * W_ + x] = fmaf(wy, bot - top, top);
    }
}

// ---------------- launch ----------------
extern "C" void kernel_launch(void* const* d_in, const int* in_sizes, int n_in,
                              void* d_out, int out_size)
{
    const float* x       = (const float*)d_in[0];  // [B,1,H,W]
    const float* rand_dx = (const float*)d_in[1];  // [B,H,W]
    const float* rand_dy = (const float*)d_in[2];  // [B,H,W]
    float* out = (float*)d_out;

    {
        dim3 grid(W_ / 32, H_ / 32, B_);
        dim3 block(32, 8);
        hblur_kernel<<<grid, block>>>(rand_dx, rand_dy);
    }
    {
        dim3 grid(W_ / 32, H_ / 32, B_);
        dim3 block(32, 8);
        vwarp_kernel<<<grid, block>>>(x, out);
    }
}